// round 16
// baseline (speedup 1.0000x reference)
#include <cuda_runtime.h>
#include <cstdint>

// Problem constants
#define S_LEN 2048
#define EMB   1024
#define HEADS 16
#define DH    64
#define BATCH 2

// Scratch (no allocations allowed)
__device__ float g_q  [(size_t)BATCH * S_LEN * EMB];   // Q (fp32)
__device__ float g_khi[(size_t)BATCH * S_LEN * EMB];   // K tf32 hi
__device__ float g_klo[(size_t)BATCH * S_LEN * EMB];   // K tf32 lo
__device__ float g_vhi[(size_t)BATCH * S_LEN * EMB];   // V tf32 hi
__device__ float g_vlo[(size_t)BATCH * S_LEN * EMB];   // V tf32 lo
__device__ float g_ctx[(size_t)BATCH * S_LEN * EMB];   // attention out (tf32-rounded)
__device__ float g_xr [(size_t)BATCH * S_LEN * EMB];   // rounded x
__device__ float g_wir[(size_t)3 * EMB * EMB];         // rounded in_proj_w
__device__ float g_wor[(size_t)EMB * EMB];             // rounded out_proj_w

// ===========================================================================
// Helpers
// ===========================================================================
__device__ __forceinline__ uint32_t smem_u32(const void* p) {
    uint32_t a;
    asm("{ .reg .u64 t; cvta.to.shared.u64 t, %1; cvt.u32.u64 %0, t; }"
        : "=r"(a) : "l"(p));
    return a;
}

__device__ __forceinline__ void cp_async16(uint32_t dst, const void* src) {
    asm volatile("cp.async.cg.shared.global [%0], [%1], 16;"
                 :: "r"(dst), "l"(src));
}
#define CP_COMMIT() asm volatile("cp.async.commit_group;")
#define CP_WAIT1()  asm volatile("cp.async.wait_group 1;")
#define CP_WAIT0()  asm volatile("cp.async.wait_group 0;")

__device__ __forceinline__ uint32_t f2tf32(float f) {
    uint32_t r;
    asm("cvt.rna.tf32.f32 %0, %1;" : "=r"(r) : "f"(f));
    return r;
}
__device__ __forceinline__ float rnd_tf32(float f) {
    return __uint_as_float(f2tf32(f));
}

// Split fp32 into tf32 hi + tf32 lo (3xTF32 error compensation)
__device__ __forceinline__ void tf32_split(float x, uint32_t& hi, uint32_t& lo) {
    hi = f2tf32(x);
    lo = f2tf32(x - __uint_as_float(hi));
}
__device__ __forceinline__ void tf32_split_f(float x, float& hi, float& lo) {
    uint32_t h, l;
    tf32_split(x, h, l);
    hi = __uint_as_float(h);
    lo = __uint_as_float(l);
}

// mma.sync m16n8k8 tf32: D += A*B, fp32 accumulate
__device__ __forceinline__ void mma_tf32(
    float* c, const uint32_t* a, const uint32_t* b)
{
    asm volatile(
        "mma.sync.aligned.m16n8k8.row.col.f32.tf32.tf32.f32 "
        "{%0,%1,%2,%3}, {%4,%5,%6,%7}, {%8,%9}, {%0,%1,%2,%3};"
        : "+f"(c[0]), "+f"(c[1]), "+f"(c[2]), "+f"(c[3])
        : "r"(a[0]), "r"(a[1]), "r"(a[2]), "r"(a[3]), "r"(b[0]), "r"(b[1]));
}

// ===========================================================================
// Merged elementwise tf32 pre-rounding (RNA) for x, w_in, w_out in ONE launch.
// ===========================================================================
__global__ __launch_bounds__(256) void round3_tf32_kernel(
    const float4* __restrict__ s0, float4* __restrict__ d0, int n0,
    const float4* __restrict__ s1, float4* __restrict__ d1, int n1,
    const float4* __restrict__ s2, float4* __restrict__ d2, int n2)
{
    const int total = n0 + n1 + n2;
    for (int i = blockIdx.x * 256 + threadIdx.x; i < total; i += gridDim.x * 256) {
        const float4* s;
        float4* d;
        int j = i;
        if (j < n0)           { s = s0; d = d0; }
        else if ((j -= n0) < n1) { s = s1; d = d1; }
        else                  { j -= n1; s = s2; d = d2; }
        float4 v = s[j];
        v.x = rnd_tf32(v.x); v.y = rnd_tf32(v.y);
        v.z = rnd_tf32(v.z); v.w = rnd_tf32(v.w);
        d[j] = v;
    }
}

// ===========================================================================
// tf32 tensor-core GEMM on PRE-ROUNDED inputs:
//   C[M,N] = A[M,K] @ B[N,K]^T + bias[N]
// CTA = 128 threads, 128x128 tile, 4 warps as 2(M) x 2(N), warp 64x64.
// NOW: DOUBLE-buffered (72KB smem) AND 2 CTAs/SM (144KB/SM fits 228KB):
// per-CTA pipeline depth 2 hides load latency within the CTA, and 16
// warps/SM hide mma dependency latency across CTAs.
// SPLIT MODE (gq != nullptr): N=3072 output routed per 1024-column region:
// Q -> gq (plain), K -> gkhi/gklo, V -> gvhi/gvlo (tf32 hi/lo).
// ===========================================================================
#define PAD      36
#define GT_ROWS  128
#define TILE_F_G (GT_ROWS * PAD)               // 4608 floats per tile
#define GBUF_F   (2 * TILE_F_G)                // A + B = 9216 floats per stage
#define GM_SMEM  (2 * GBUF_F * 4)              // 73728 bytes (two stages)

__global__ __launch_bounds__(128, 2) void gemm_mma(
    const float* __restrict__ A, const float* __restrict__ B,
    const float* __restrict__ bias, float* __restrict__ C,
    int M, int N, int K,
    float* __restrict__ gq,
    float* __restrict__ gkhi, float* __restrict__ gklo,
    float* __restrict__ gvhi, float* __restrict__ gvlo)
{
    extern __shared__ float smem[];
    const int tid  = threadIdx.x;
    const int wid  = tid >> 5;        // 0..3
    const int lane = tid & 31;
    const int wm   = wid >> 1;        // 0..1 -> 64-row band
    const int wn   = wid & 1;         // 0..1 -> 64-col band
    const int g    = lane >> 2;
    const int tig  = lane & 3;
    const int bm   = blockIdx.y * 128;
    const int bn   = blockIdx.x * 128;

    float acc[4][8][4];
    #pragma unroll
    for (int mt = 0; mt < 4; mt++)
        #pragma unroll
        for (int nt = 0; nt < 8; nt++)
            #pragma unroll
            for (int i = 0; i < 4; i++)
                acc[mt][nt][i] = 0.0f;

    auto fill = [&](int buf, int kc) {
        const int k0 = kc << 5;
        const uint32_t sA = smem_u32(smem + buf * GBUF_F);
        const uint32_t sB = sA + TILE_F_G * 4;
        #pragma unroll
        for (int i = 0; i < 8; i++) {              // A: 128 rows x 8 float4
            const int id = tid + (i << 7);
            const int r  = id >> 3;
            const int c  = id & 7;
            cp_async16(sA + (uint32_t)(r * PAD + c * 4) * 4,
                       A + (size_t)(bm + r) * K + k0 + c * 4);
        }
        #pragma unroll
        for (int i = 0; i < 8; i++) {              // B: 128 rows x 8 float4
            const int id = tid + (i << 7);
            const int r  = id >> 3;
            const int c  = id & 7;
            cp_async16(sB + (uint32_t)(r * PAD + c * 4) * 4,
                       B + (size_t)(bn + r) * K + k0 + c * 4);
        }
        CP_COMMIT();
    };

    const int NK = K >> 5;
    fill(0, 0);
    fill(1, 1);

    for (int kc = 0; kc < NK; kc++) {
        const int buf = kc & 1;
        if (kc == NK - 1) { CP_WAIT0(); } else { CP_WAIT1(); }
        __syncthreads();

        const float* sA = smem + buf * GBUF_F;
        const float* sB = sA + TILE_F_G;

        #pragma unroll
        for (int ks = 0; ks < 4; ks++) {
            const int kb = ks * 8 + tig;
            uint32_t af[4][4], bf[8][2];
            #pragma unroll
            for (int mt = 0; mt < 4; mt++) {
                const float* p = sA + (wm * 64 + mt * 16 + g) * PAD + kb;
                af[mt][0] = __float_as_uint(p[0]);
                af[mt][1] = __float_as_uint(p[8 * PAD]);
                af[mt][2] = __float_as_uint(p[4]);
                af[mt][3] = __float_as_uint(p[8 * PAD + 4]);
            }
            #pragma unroll
            for (int nt = 0; nt < 8; nt++) {
                const float* p = sB + (wn * 64 + nt * 8 + g) * PAD + kb;
                bf[nt][0] = __float_as_uint(p[0]);
                bf[nt][1] = __float_as_uint(p[4]);
            }
            #pragma unroll
            for (int mt = 0; mt < 4; mt++)
                #pragma unroll
                for (int nt = 0; nt < 8; nt++)
                    mma_tf32(acc[mt][nt], af[mt], bf[nt]);
        }
        __syncthreads();

        if (kc + 2 < NK) fill(buf, kc + 2);
    }

    // ---- epilogue ----
    const int region = (gq != nullptr) ? (bn >> 10) : -1;   // 0=Q, 1=K, 2=V
    #pragma unroll
    for (int mt = 0; mt < 4; mt++) {
        const int row0 = bm + wm * 64 + mt * 16 + g;
        #pragma unroll
        for (int nt = 0; nt < 8; nt++) {
            const int col = bn + wn * 64 + nt * 8 + 2 * tig;
            const float b0 = bias[col], b1 = bias[col + 1];
            float2 o0, o1;
            o0.x = acc[mt][nt][0] + b0;  o0.y = acc[mt][nt][1] + b1;
            o1.x = acc[mt][nt][2] + b0;  o1.y = acc[mt][nt][3] + b1;

            if (region < 0) {
                *(float2*)(C + (size_t)row0 * N + col)       = o0;
                *(float2*)(C + (size_t)(row0 + 8) * N + col) = o1;
            } else {
                const int lcol = col & 1023;
                const size_t i0 = (size_t)row0 * EMB + lcol;
                const size_t i1 = (size_t)(row0 + 8) * EMB + lcol;
                if (region == 0) {
                    *(float2*)(gq + i0) = o0;
                    *(float2*)(gq + i1) = o1;
                } else {
                    float2 h0, l0, h1, l1;
                    tf32_split_f(o0.x, h0.x, l0.x);
                    tf32_split_f(o0.y, h0.y, l0.y);
                    tf32_split_f(o1.x, h1.x, l1.x);
                    tf32_split_f(o1.y, h1.y, l1.y);
                    float* hi_dst = (region == 1) ? gkhi : gvhi;
                    float* lo_dst = (region == 1) ? gklo : gvlo;
                    *(float2*)(hi_dst + i0) = h0;
                    *(float2*)(lo_dst + i0) = l0;
                    *(float2*)(hi_dst + i1) = h1;
                    *(float2*)(lo_dst + i1) = l1;
                }
            }
        }
    }
}

// ===========================================================================
// Tensor-core flash attention, 3xTF32 compensated, pre-split K/V from global.
// UNCHANGED from round 14/15 (best-known): 2 CTAs/SM, 128 threads x 64
// queries, 64-key tiles, single-buffered KV; peer CTA hides per-tile waits.
// ===========================================================================
#define AP        68                            // padded row (floats)
#define QT_F      (64 * AP)                     // 4352 floats (64 queries)
#define KVT_F     (64 * AP)                     // 4352 floats (64 keys)
#define A_KHI     QT_F
#define A_KLO     (QT_F + 1 * KVT_F)
#define A_VHI     (QT_F + 2 * KVT_F)
#define A_VLO     (QT_F + 3 * KVT_F)
#define ATT_SMEM  ((QT_F + 4 * KVT_F) * 4)      // 87040 bytes

__global__ __launch_bounds__(128, 2) void attn_mma_kernel(
    const float* __restrict__ gq,
    const float* __restrict__ gkhi, const float* __restrict__ gklo,
    const float* __restrict__ gvhi, const float* __restrict__ gvlo,
    float* __restrict__ ctx)
{
    extern __shared__ float smem[];
    const int tid  = threadIdx.x;
    const int w    = tid >> 5;          // 0..3
    const int lane = tid & 31;
    const int g    = lane >> 2;
    const int tig  = lane & 3;

    const int qt = gridDim.x - 1 - blockIdx.x;     // heaviest tiles first, qt 0..31
    const int bh = blockIdx.y;
    const int b  = bh >> 4;
    const int h  = bh & 15;

    const size_t bbase = (size_t)b * S_LEN * EMB + h * DH;
    const int ktmax = qt;                           // 64-key tiles

    // ---- Q stage (64 rows x 16 float4; bundled with first KV fill) ----
    {
        const float* Qsrc = gq + bbase + (size_t)(qt * 64) * EMB;
        const uint32_t qs = smem_u32(smem);
        #pragma unroll
        for (int i = 0; i < 8; i++) {
            const int id = tid + (i << 7);
            const int r = id >> 4, c4 = id & 15;
            cp_async16(qs + (uint32_t)((r * AP + c4 * 4) * 4),
                       Qsrc + (size_t)r * EMB + c4 * 4);
        }
    }

    auto fill_kv = [&](int kt) {
        const size_t tbase = bbase + (size_t)(kt * 64) * EMB;
        const uint32_t kh = smem_u32(smem + A_KHI);
        const uint32_t kl = smem_u32(smem + A_KLO);
        const uint32_t vh = smem_u32(smem + A_VHI);
        const uint32_t vl = smem_u32(smem + A_VLO);
        #pragma unroll
        for (int i = 0; i < 8; i++) {               // 64 rows x 16 float4 / 128 thr
            const int id = tid + (i << 7);
            const int r = id >> 4, c4 = id & 15;
            const uint32_t so = (uint32_t)((r * AP + c4 * 4) * 4);
            const size_t go = tbase + (size_t)r * EMB + c4 * 4;
            cp_async16(kh + so, gkhi + go);
            cp_async16(kl + so, gklo + go);
            cp_async16(vh + so, gvhi + go);
            cp_async16(vl + so, gvlo + go);
        }
        CP_COMMIT();
    };

    fill_kv(0);          // one group: Q + KV(0)

    uint32_t Qh[8][4], Ql[8][4];
    float S[8][4];       // 64 keys = 8 n8 fragments
    float O[8][4];       // d = 64   = 8 n8 fragments
    float m0 = -1e30f, m1 = -1e30f, l0 = 0.0f, l1 = 0.0f;
    #pragma unroll
    for (int nt = 0; nt < 8; nt++)
        #pragma unroll
        for (int i = 0; i < 4; i++)
            O[nt][i] = 0.0f;

    for (int kt = 0; kt <= ktmax; kt++) {
        CP_WAIT0();
        __syncthreads();   // KV(kt) landed; peer CTA's mma hides this wait

        if (kt == 0) {   // Q fragments, split into tf32 hi/lo once
            const float* Qp = smem + (16 * w + g) * AP + tig;
            #pragma unroll
            for (int kb = 0; kb < 8; kb++) {
                tf32_split(Qp[kb * 8],              Qh[kb][0], Ql[kb][0]);
                tf32_split(Qp[8 * AP + kb * 8],     Qh[kb][1], Ql[kb][1]);
                tf32_split(Qp[kb * 8 + 4],          Qh[kb][2], Ql[kb][2]);
                tf32_split(Qp[8 * AP + kb * 8 + 4], Qh[kb][3], Ql[kb][3]);
            }
        }

        const float* Khl = smem + A_KHI + g * AP + tig;
        const float* Kll = smem + A_KLO + g * AP + tig;
        const float* Vhl = smem + A_VHI + 2 * tig * AP + g;
        const float* Vll = smem + A_VLO + 2 * tig * AP + g;

        // ---- S = Q K^T (3xTF32), 8 n8 key fragments ----
        #pragma unroll
        for (int nt = 0; nt < 8; nt++)
            #pragma unroll
            for (int i = 0; i < 4; i++)
                S[nt][i] = 0.0f;

        #pragma unroll
        for (int kb = 0; kb < 8; kb++) {
            #pragma unroll
            for (int nt = 0; nt < 8; nt++) {
                const int so = nt * (8 * AP) + kb * 8;
                uint32_t bh_[2], bl_[2];
                bh_[0] = __float_as_uint(Khl[so]);
                bh_[1] = __float_as_uint(Khl[so + 4]);
                bl_[0] = __float_as_uint(Kll[so]);
                bl_[1] = __float_as_uint(Kll[so + 4]);
                mma_tf32(S[nt], Qh[kb], bh_);
                mma_tf32(S[nt], Qh[kb], bl_);
                mma_tf32(S[nt], Ql[kb], bh_);
            }
        }

        // ---- causal mask (single diagonal tile) ----
        if (kt == qt) {
            const int q0 = 16 * w + g;
            const int q1 = q0 + 8;
            #pragma unroll
            for (int nt = 0; nt < 8; nt++) {
                const int kc = nt * 8 + 2 * tig;
                if (kc     > q0) S[nt][0] = -1e30f;
                if (kc + 1 > q0) S[nt][1] = -1e30f;
                if (kc     > q1) S[nt][2] = -1e30f;
                if (kc + 1 > q1) S[nt][3] = -1e30f;
            }
        }

        // ---- online softmax (scale 0.125 folded into exp) ----
        float t0 = -1e30f, t1 = -1e30f;
        #pragma unroll
        for (int nt = 0; nt < 8; nt++) {
            t0 = fmaxf(t0, fmaxf(S[nt][0], S[nt][1]));
            t1 = fmaxf(t1, fmaxf(S[nt][2], S[nt][3]));
        }
        #pragma unroll
        for (int o = 1; o <= 2; o <<= 1) {
            t0 = fmaxf(t0, __shfl_xor_sync(0xffffffffu, t0, o));
            t1 = fmaxf(t1, __shfl_xor_sync(0xffffffffu, t1, o));
        }
        const float mn0 = fmaxf(m0, t0), mn1 = fmaxf(m1, t1);
        const float c0 = __expf(0.125f * (m0 - mn0));
        const float c1 = __expf(0.125f * (m1 - mn1));
        m0 = mn0; m1 = mn1;

        float rs0 = 0.0f, rs1 = 0.0f;
        #pragma unroll
        for (int nt = 0; nt < 8; nt++) {
            S[nt][0] = __expf(0.125f * (S[nt][0] - mn0));
            S[nt][1] = __expf(0.125f * (S[nt][1] - mn0));
            S[nt][2] = __expf(0.125f * (S[nt][2] - mn1));
            S[nt][3] = __expf(0.125f * (S[nt][3] - mn1));
            rs0 += S[nt][0] + S[nt][1];
            rs1 += S[nt][2] + S[nt][3];
        }
        #pragma unroll
        for (int o = 1; o <= 2; o <<= 1) {
            rs0 += __shfl_xor_sync(0xffffffffu, rs0, o);
            rs1 += __shfl_xor_sync(0xffffffffu, rs1, o);
        }
        l0 = l0 * c0 + rs0;
        l1 = l1 * c1 + rs1;

        #pragma unroll
        for (int nt = 0; nt < 8; nt++) {
            O[nt][0] *= c0; O[nt][1] *= c0;
            O[nt][2] *= c1; O[nt][3] *= c1;
        }

        // ---- O += P V (3-term compensated; k-permuted layout) ----
        #pragma unroll
        for (int kb = 0; kb < 8; kb++) {
            uint32_t aPh[4], aPl[4];
            tf32_split(S[kb][0], aPh[0], aPl[0]);
            tf32_split(S[kb][2], aPh[1], aPl[1]);
            tf32_split(S[kb][1], aPh[2], aPl[2]);
            tf32_split(S[kb][3], aPh[3], aPl[3]);
            #pragma unroll
            for (int nt = 0; nt < 8; nt++) {
                const int so = kb * (8 * AP) + nt * 8;
                uint32_t bh_[2], bl_[2];
                bh_[0] = __float_as_uint(Vhl[so]);
                bh_[1] = __float_as_uint(Vhl[so + AP]);
                bl_[0] = __float_as_uint(Vll[so]);
                bl_[1] = __float_as_uint(Vll[so + AP]);
                mma_tf32(O[nt], aPh, bh_);
                mma_tf32(O[nt], aPl, bh_);
                mma_tf32(O[nt], aPh, bl_);
            }
        }

        __syncthreads();   // all readers done before single-buffer refill
        if (kt < ktmax) fill_kv(kt + 1);
    }

    // ---- normalize + tf32-round + write ctx (gemm2 reads raw bits) ----
    const float i0 = 1.0f / l0, i1 = 1.0f / l1;
    const size_t row0 = (size_t)b * S_LEN + qt * 64 + 16 * w + g;
    #pragma unroll
    for (int nt = 0; nt < 8; nt++) {
        const int col = h * DH + nt * 8 + 2 * tig;
        float2 o0, o1;
        o0.x = rnd_tf32(O[nt][0] * i0);  o0.y = rnd_tf32(O[nt][1] * i0);
        o1.x = rnd_tf32(O[nt][2] * i1);  o1.y = rnd_tf32(O[nt][3] * i1);
        *(float2*)(ctx + row0 * EMB + col)       = o0;
        *(float2*)(ctx + (row0 + 8) * EMB + col) = o1;
    }
}

// ===========================================================================
// Launch: merged pre-round -> gemm1 (split epilogue) -> attention -> gemm2
// ===========================================================================
extern "C" void kernel_launch(void* const* d_in, const int* in_sizes, int n_in,
                              void* d_out, int out_size)
{
    const float* x     = (const float*)d_in[0];
    const float* w_in  = (const float*)d_in[1];
    const float* b_in  = (const float*)d_in[2];
    const float* w_out = (const float*)d_in[3];
    const float* b_out = (const float*)d_in[4];
    float* out = (float*)d_out;

    float *gq, *gkhi, *gklo, *gvhi, *gvlo, *ctx, *xr, *wir, *wor;
    cudaGetSymbolAddress((void**)&gq,   g_q);
    cudaGetSymbolAddress((void**)&gkhi, g_khi);
    cudaGetSymbolAddress((void**)&gklo, g_klo);
    cudaGetSymbolAddress((void**)&gvhi, g_vhi);
    cudaGetSymbolAddress((void**)&gvlo, g_vlo);
    cudaGetSymbolAddress((void**)&ctx,  g_ctx);
    cudaGetSymbolAddress((void**)&xr,   g_xr);
    cudaGetSymbolAddress((void**)&wir,  g_wir);
    cudaGetSymbolAddress((void**)&wor,  g_wor);

    const int M = BATCH * S_LEN;   // 4096

    static bool attr_set = false;
    if (!attr_set) {
        cudaFuncSetAttribute(gemm_mma,
                             cudaFuncAttributeMaxDynamicSharedMemorySize, GM_SMEM);
        cudaFuncSetAttribute(attn_mma_kernel,
                             cudaFuncAttributeMaxDynamicSharedMemorySize, ATT_SMEM);
        attr_set = true;
    }

    // 0) pre-round x, w_in, w_out to tf32 (RNA), one merged launch
    {
        const int nx = M * EMB / 4;            // 1048576
        const int nw = 3 * EMB * EMB / 4;      // 786432
        const int no = EMB * EMB / 4;          // 262144
        round3_tf32_kernel<<<1184, 256>>>(
            (const float4*)x,     (float4*)xr,  nx,
            (const float4*)w_in,  (float4*)wir, nw,
            (const float4*)w_out, (float4*)wor, no);
    }

    // 1) qkv projection with split epilogue: Q plain, K/V tf32 hi+lo
    gemm_mma<<<dim3((3 * EMB) / 128, M / 128), 128, GM_SMEM>>>(
        xr, wir, b_in, nullptr, M, 3 * EMB, EMB,
        gq, gkhi, gklo, gvhi, gvlo);

    // 2) fused causal attention -> ctx [4096, 1024] (tf32-rounded)
    attn_mma_kernel<<<dim3(S_LEN / 64, BATCH * HEADS), 128, ATT_SMEM>>>(
        gq, gkhi, gklo, gvhi, gvlo, ctx);

    // 3) out = ctx @ out_proj_w^T + out_proj_b   [4096, 1024]
    gemm_mma<<<dim3(EMB / 128, M / 128), 128, GM_SMEM>>>(
        ctx, wor, b_out, out, M, EMB, EMB,
        nullptr, nullptr, nullptr, nullptr, nullptr);
}